// round 4
// baseline (speedup 1.0000x reference)
#include <cuda_runtime.h>
#include <cstdint>

#define N 8192
#define NW 128          // max 64-bit words per active mask row (N/64)
typedef unsigned long long u64;
typedef unsigned int u32;

#define ACT_BIT (1ull << 13)          // active flag inside key, masked out of compares
#define KEY_CMP_MASK (~ACT_BIT)

// ---------------- device globals (zero-initialized at module load) ----------------
__device__ u32 g_maxbox;
__device__ int g_cnt;      // valid boxes (score > 0.25)
__device__ int g_cnt_a;    // active valid boxes (positive area)
__device__ float g_x1[N], g_y1[N], g_x2[N], g_y2[N], g_sc[N];
__device__ u64 g_keys[N];  // (~mono(score))<<32 | act<<13 | idx(13 bits)
__device__ float g_sx1[N], g_sy1[N], g_sx2[N], g_sy2[N], g_ssc[N], g_sar[N]; // sorted actives
__device__ int g_apos[N];  // sorted-active rank -> overall sorted position (output row)
__device__ u64 g_mask[N * NW];   // suppression bitmask among actives

__device__ __forceinline__ u32 fmono(float f) {
    u32 u = __float_as_uint(f);
    return (u & 0x80000000u) ? ~u : (u | 0x80000000u);
}

// decode boxes, global coord max, compact valid keys (+active flag), zero output
__global__ void k_prep(const float* __restrict__ p, float* __restrict__ out) {
    int i = blockIdx.x * blockDim.x + threadIdx.x;   // grid covers exactly N
    float cx = p[i], cy = p[N + i], pw = p[2*N + i], ph = p[3*N + i], s = p[4*N + i];
    float x1 = cx - pw*0.5f, y1 = cy - ph*0.5f, x2 = cx + pw*0.5f, y2 = cy + ph*0.5f;
    g_x1[i]=x1; g_y1[i]=y1; g_x2[i]=x2; g_y2[i]=y2; g_sc[i]=s;

    u32 m = fmono(fmaxf(fmaxf(x1,x2), fmaxf(y1,y2)));
    #pragma unroll
    for (int o = 16; o; o >>= 1) m = max(m, __shfl_xor_sync(0xffffffffu, m, o));
    if ((threadIdx.x & 31) == 0) atomicMax(&g_maxbox, m);

    if (s > 0.25f) {
        bool act = (x2 > x1) && (y2 > y1);     // positive area: participates in NMS
        int slot = atomicAdd(&g_cnt, 1);
        if (act) atomicAdd(&g_cnt_a, 1);
        g_keys[slot] = ((u64)(~fmono(s)) << 32) | (act ? ACT_BIT : 0ull) | (u32)i;
    }
    for (int k = i; k < N*6; k += N) out[k] = 0.0f;   // zero full output
}

// O(n^2) rank sort, j-loop split 4-ways per i. Passive boxes (zero area) are
// never suppressed and never suppress -> emitted directly here.
__global__ __launch_bounds__(1024) void k_rank(float* __restrict__ out) {
    __shared__ u64 sk[1024];
    int cnt = g_cnt;
    if (blockIdx.x * 256 >= cnt) return;
    int tid = threadIdx.x;
    int i = blockIdx.x * 256 + (tid >> 2);
    int part = tid & 3;

    u64 ki = (i < cnt) ? g_keys[i] : ~0ull;
    u64 kim = ki & KEY_CMP_MASK;
    int rank_all = 0, rank_act = 0;

    for (int base = 0; base < cnt; base += 1024) {
        int lim = min(1024, cnt - base);
        __syncthreads();
        for (int t = tid; t < lim; t += 1024) sk[t] = g_keys[base + t];
        __syncthreads();
        for (int j = part; j < lim; j += 4) {
            u64 kj = sk[j];
            bool lt = (kj & KEY_CMP_MASK) < kim;
            rank_all += lt;
            rank_act += (lt && (kj & ACT_BIT));
        }
    }
    rank_all += __shfl_xor_sync(0xffffffffu, rank_all, 1);
    rank_all += __shfl_xor_sync(0xffffffffu, rank_all, 2);
    rank_act += __shfl_xor_sync(0xffffffffu, rank_act, 1);
    rank_act += __shfl_xor_sync(0xffffffffu, rank_act, 2);

    if (part == 0 && i < cnt) {
        int o = (int)(ki & 0x1FFFull);
        bool act = (ki & ACT_BIT) != 0ull;
        float x1 = g_x1[o], y1 = g_y1[o], x2 = g_x2[o], y2 = g_y2[o], s = g_sc[o];
        if (act) {
            int r = rank_act;
            g_sx1[r]=x1; g_sy1[r]=y1; g_sx2[r]=x2; g_sy2[r]=y2;
            g_ssc[r]=s;  g_sar[r]=(x2-x1)*(y2-y1);
            g_apos[r]=rank_all;
        } else {
            float f = (g_maxbox <= 0xBF800000u) ? 1.0f : (1.0f / 416.0f);
            float* o6 = out + rank_all * 6;
            o6[0]=x1*f; o6[1]=y1*f; o6[2]=x2*f; o6[3]=y2*f; o6[4]=s; o6[5]=0.0f;
        }
    }
}

// pairwise IoU bitmask among actives: grid-stride over actual upper-triangle tiles
__global__ __launch_bounds__(256) void k_mask() {
    int cnt = g_cnt_a;
    if (cnt == 0) return;
    int W = (cnt + 63) >> 6;
    int itiles = (cnt + 15) >> 4;
    int wtiles = (W + 15) >> 4;
    int ntiles = itiles * wtiles;

    __shared__ float jx1[1040], jy1[1040], jx2[1040], jy2[1040], jar[1040];
    int tid = threadIdx.x;

    for (int t = blockIdx.x; t < ntiles; t += gridDim.x) {
        int i0 = (t / wtiles) * 16;
        int w0 = (t % wtiles) * 16;
        if ((w0 + 16) * 64 <= i0) continue;   // fully below diagonal (uniform per block)

        __syncthreads();                       // smem reuse guard
        for (int tt = tid; tt < 1024; tt += 256) {
            int j = w0 * 64 + tt;
            int jm = (tt >> 6) * 65 + (tt & 63);   // +1 pad per 64 -> conflict-free
            bool ok = j < cnt;
            jx1[jm] = ok ? g_sx1[j] :  3.4e38f;
            jy1[jm] = ok ? g_sy1[j] :  3.4e38f;
            jx2[jm] = ok ? g_sx2[j] : -3.4e38f;
            jy2[jm] = ok ? g_sy2[j] : -3.4e38f;
            jar[jm] = ok ? g_sar[j] : 0.0f;
        }
        __syncthreads();

        int r  = tid >> 4;          // row within tile
        int wl = tid & 15;          // word within tile
        int i = i0 + r;
        int w = w0 + wl;
        if (i < cnt && w < W) {
            float ix1 = g_sx1[i], iy1 = g_sy1[i], ix2 = g_sx2[i], iy2 = g_sy2[i], iar = g_sar[i];
            int base = wl * 65;
            u64 bits = 0;
            #pragma unroll 8
            for (int jj = 0; jj < 64; jj++) {
                float bx1 = jx1[base + jj], by1 = jy1[base + jj];
                float bx2 = jx2[base + jj], by2 = jy2[base + jj], ba = jar[base + jj];
                float xx1 = fmaxf(ix1, bx1), yy1 = fmaxf(iy1, by1);
                float xx2 = fminf(ix2, bx2), yy2 = fminf(iy2, by2);
                float dx = fmaxf(xx2 - xx1, 0.0f), dy = fmaxf(yy2 - yy1, 0.0f);
                float inter = dx * dy;
                float uni = iar + ba - inter;
                bool pred = (inter > 0.45f * uni) && (uni > 0.0f);
                bits |= ((u64)pred) << jj;
            }
            g_mask[(size_t)i * NW + w] = bits;
        }
    }
}

// single-WARP greedy scan: no block barriers, branchless resolve, remv in registers
__global__ __launch_bounds__(32) void k_scan(float* __restrict__ out) {
    __shared__ u64 buf[2][64];
    int lane = threadIdx.x;
    int cnt = g_cnt_a;
    int W = (cnt + 63) >> 6;
    float f = (g_maxbox <= 0xBF800000u) ? 1.0f : (1.0f / 416.0f);

    // remv bitset in registers: lane owns words lane, lane+32, lane+64, lane+96
    u64 rv0 = 0, rv1 = 0, rv2 = 0, rv3 = 0;

    if (cnt > 0) {
        // preload resolve column of chunk 0
        int r0 = 2 * lane, r1 = 2 * lane + 1;
        buf[0][r0] = (r0 < cnt) ? g_mask[(size_t)r0 * NW] : 0ull;
        buf[0][r1] = (r1 < cnt) ? g_mask[(size_t)r1 * NW] : 0ull;
    }
    __syncwarp();

    for (int c = 0; c < W; c++) {
        int cb = c & 1;

        // prefetch chunk c+1's resolve column into regs (latency hidden behind resolve)
        u64 p0 = 0, p1 = 0;
        if (c + 1 < W) {
            int r0 = (c + 1) * 64 + 2 * lane, r1 = r0 + 1;
            if (r0 < cnt) p0 = g_mask[(size_t)r0 * NW + (c + 1)];
            if (r1 < cnt) p1 = g_mask[(size_t)r1 * NW + (c + 1)];
        }

        // fetch this chunk's already-suppressed word from its owning lane
        int sel = c >> 5, src = c & 31;
        u64 v = (sel == 0) ? rv0 : (sel == 1) ? rv1 : (sel == 2) ? rv2 : rv3;
        u64 sup = __shfl_sync(0xffffffffu, v, src);

        // branchless serial resolve (all lanes redundantly, lockstep)
        u64 kb = 0;
        #pragma unroll
        for (int b = 0; b < 64; b++) {
            u64 keep = ((~sup) >> b) & 1ull;
            kb |= keep << b;
            sup |= buf[cb][b] & (0ull - keep);
        }
        int lim = cnt - c * 64;
        if (lim < 64) kb &= (1ull << lim) - 1ull;

        // emit kept rows (lane handles rows lane and lane+32); 24B rows are 8B-aligned
        #pragma unroll
        for (int h = 0; h < 2; h++) {
            int b = lane + 32 * h;
            int k = c * 64 + b;
            if (k < cnt && ((kb >> b) & 1ull)) {
                float* o = out + g_apos[k] * 6;
                *(float2*)(o)     = make_float2(g_sx1[k] * f, g_sy1[k] * f);
                *(float2*)(o + 2) = make_float2(g_sx2[k] * f, g_sy2[k] * f);
                *(float2*)(o + 4) = make_float2(g_ssc[k], 0.0f);
            }
        }

        // apply kept rows' masks to owned future words (iterate kept bits only)
        size_t rowbase = (size_t)c * 64 * NW;
        #pragma unroll
        for (int q = 0; q < 4; q++) {
            int w = lane + 32 * q;
            if (w > c && w < W) {
                u64 acc = 0, t = kb;
                while (t) {
                    int b = __ffsll((long long)t) - 1;
                    t &= t - 1;
                    acc |= g_mask[rowbase + (size_t)b * NW + w];
                }
                if (q == 0) rv0 |= acc; else if (q == 1) rv1 |= acc;
                else if (q == 2) rv2 |= acc; else rv3 |= acc;
            }
        }

        // publish prefetched column for next chunk
        if (c + 1 < W) {
            buf[(c + 1) & 1][2 * lane]     = p0;
            buf[(c + 1) & 1][2 * lane + 1] = p1;
        }
        __syncwarp();
    }

    // reset counters for the next graph replay
    if (lane == 0) { g_cnt = 0; g_cnt_a = 0; g_maxbox = 0u; }
}

extern "C" void kernel_launch(void* const* d_in, const int* in_sizes, int n_in,
                              void* d_out, int out_size) {
    const float* preds = (const float*)d_in[0];
    float* out = (float*)d_out;

    k_prep<<<N / 256, 256>>>(preds, out);
    k_rank<<<N / 256, 1024>>>(out);
    k_mask<<<128, 256>>>();
    k_scan<<<1, 32>>>(out);
}

// round 5
// speedup vs baseline: 2.1371x; 2.1371x over previous
#include <cuda_runtime.h>
#include <cstdint>

#define N 8192
#define NW 128          // max 64-bit words per active mask row (N/64)
typedef unsigned long long u64;
typedef unsigned int u32;

#define ACT_BIT (1ull << 13)          // active flag inside key, masked out of compares
#define KEY_CMP_MASK (~ACT_BIT)

// ---------------- device globals (zero-initialized at module load) ----------------
__device__ u32 g_maxbox;
__device__ int g_cnt;      // valid boxes (score > 0.25)
__device__ int g_cnt_a;    // active valid boxes (positive area)
__device__ float g_x1[N], g_y1[N], g_x2[N], g_y2[N], g_sc[N];
__device__ u64 g_keys[N];  // (~mono(score))<<32 | act<<13 | idx(13 bits)
__device__ float g_sx1[N], g_sy1[N], g_sx2[N], g_sy2[N], g_ssc[N], g_sar[N]; // sorted actives
__device__ int g_apos[N];  // sorted-active rank -> overall sorted position (output row)
__device__ u64 g_mask[N * NW];   // suppression bitmask among actives

__device__ __forceinline__ u32 fmono(float f) {
    u32 u = __float_as_uint(f);
    return (u & 0x80000000u) ? ~u : (u | 0x80000000u);
}

// decode boxes, global coord max, compact valid keys (+active flag), zero output
__global__ void k_prep(const float* __restrict__ p, float* __restrict__ out) {
    int i = blockIdx.x * blockDim.x + threadIdx.x;   // grid covers exactly N
    float cx = p[i], cy = p[N + i], pw = p[2*N + i], ph = p[3*N + i], s = p[4*N + i];
    float x1 = cx - pw*0.5f, y1 = cy - ph*0.5f, x2 = cx + pw*0.5f, y2 = cy + ph*0.5f;
    g_x1[i]=x1; g_y1[i]=y1; g_x2[i]=x2; g_y2[i]=y2; g_sc[i]=s;

    u32 m = fmono(fmaxf(fmaxf(x1,x2), fmaxf(y1,y2)));
    #pragma unroll
    for (int o = 16; o; o >>= 1) m = max(m, __shfl_xor_sync(0xffffffffu, m, o));
    if ((threadIdx.x & 31) == 0) atomicMax(&g_maxbox, m);

    if (s > 0.25f) {
        bool act = (x2 > x1) && (y2 > y1);     // positive area: participates in NMS
        int slot = atomicAdd(&g_cnt, 1);
        if (act) atomicAdd(&g_cnt_a, 1);
        g_keys[slot] = ((u64)(~fmono(s)) << 32) | (act ? ACT_BIT : 0ull) | (u32)i;
    }
    for (int k = i; k < N*6; k += N) out[k] = 0.0f;   // zero full output
}

// O(n^2) rank sort, j-loop split 4-ways per i. Passive boxes (zero area) are
// never suppressed and never suppress -> emitted directly here.
__global__ __launch_bounds__(1024) void k_rank(float* __restrict__ out) {
    __shared__ u64 sk[1024];
    int cnt = g_cnt;
    if (blockIdx.x * 256 >= cnt) return;
    int tid = threadIdx.x;
    int i = blockIdx.x * 256 + (tid >> 2);
    int part = tid & 3;

    u64 ki = (i < cnt) ? g_keys[i] : ~0ull;
    u64 kim = ki & KEY_CMP_MASK;
    int rank_all = 0, rank_act = 0;

    for (int base = 0; base < cnt; base += 1024) {
        int lim = min(1024, cnt - base);
        __syncthreads();
        for (int t = tid; t < lim; t += 1024) sk[t] = g_keys[base + t];
        __syncthreads();
        for (int j = part; j < lim; j += 4) {
            u64 kj = sk[j];
            bool lt = (kj & KEY_CMP_MASK) < kim;
            rank_all += lt;
            rank_act += (lt && (kj & ACT_BIT));
        }
    }
    rank_all += __shfl_xor_sync(0xffffffffu, rank_all, 1);
    rank_all += __shfl_xor_sync(0xffffffffu, rank_all, 2);
    rank_act += __shfl_xor_sync(0xffffffffu, rank_act, 1);
    rank_act += __shfl_xor_sync(0xffffffffu, rank_act, 2);

    if (part == 0 && i < cnt) {
        int o = (int)(ki & 0x1FFFull);
        bool act = (ki & ACT_BIT) != 0ull;
        float x1 = g_x1[o], y1 = g_y1[o], x2 = g_x2[o], y2 = g_y2[o], s = g_sc[o];
        if (act) {
            int r = rank_act;
            g_sx1[r]=x1; g_sy1[r]=y1; g_sx2[r]=x2; g_sy2[r]=y2;
            g_ssc[r]=s;  g_sar[r]=(x2-x1)*(y2-y1);
            g_apos[r]=rank_all;
        } else {
            float f = (g_maxbox <= 0xBF800000u) ? 1.0f : (1.0f / 416.0f);
            float* o6 = out + rank_all * 6;
            o6[0]=x1*f; o6[1]=y1*f; o6[2]=x2*f; o6[3]=y2*f; o6[4]=s; o6[5]=0.0f;
        }
    }
}

// pairwise IoU bitmask among actives: grid-stride over actual upper-triangle tiles
__global__ __launch_bounds__(256) void k_mask() {
    int cnt = g_cnt_a;
    if (cnt == 0) return;
    int W = (cnt + 63) >> 6;
    int itiles = (cnt + 15) >> 4;
    int wtiles = (W + 15) >> 4;
    int ntiles = itiles * wtiles;

    __shared__ float jx1[1040], jy1[1040], jx2[1040], jy2[1040], jar[1040];
    int tid = threadIdx.x;

    for (int t = blockIdx.x; t < ntiles; t += gridDim.x) {
        int i0 = (t / wtiles) * 16;
        int w0 = (t % wtiles) * 16;
        if ((w0 + 16) * 64 <= i0) continue;   // fully below diagonal (uniform per block)

        __syncthreads();                       // smem reuse guard
        for (int tt = tid; tt < 1024; tt += 256) {
            int j = w0 * 64 + tt;
            int jm = (tt >> 6) * 65 + (tt & 63);   // +1 pad per 64 -> conflict-free
            bool ok = j < cnt;
            jx1[jm] = ok ? g_sx1[j] :  3.4e38f;
            jy1[jm] = ok ? g_sy1[j] :  3.4e38f;
            jx2[jm] = ok ? g_sx2[j] : -3.4e38f;
            jy2[jm] = ok ? g_sy2[j] : -3.4e38f;
            jar[jm] = ok ? g_sar[j] : 0.0f;
        }
        __syncthreads();

        int r  = tid >> 4;          // row within tile
        int wl = tid & 15;          // word within tile
        int i = i0 + r;
        int w = w0 + wl;
        if (i < cnt && w < W) {
            float ix1 = g_sx1[i], iy1 = g_sy1[i], ix2 = g_sx2[i], iy2 = g_sy2[i], iar = g_sar[i];
            int base = wl * 65;
            u64 bits = 0;
            #pragma unroll 8
            for (int jj = 0; jj < 64; jj++) {
                float bx1 = jx1[base + jj], by1 = jy1[base + jj];
                float bx2 = jx2[base + jj], by2 = jy2[base + jj], ba = jar[base + jj];
                float xx1 = fmaxf(ix1, bx1), yy1 = fmaxf(iy1, by1);
                float xx2 = fminf(ix2, bx2), yy2 = fminf(iy2, by2);
                float dx = fmaxf(xx2 - xx1, 0.0f), dy = fmaxf(yy2 - yy1, 0.0f);
                float inter = dx * dy;
                float uni = iar + ba - inter;
                bool pred = (inter > 0.45f * uni) && (uni > 0.0f);
                bits |= ((u64)pred) << jj;
            }
            g_mask[(size_t)i * NW + w] = bits;
        }
    }
}

// greedy scan, 128 threads: warp0 = branchless resolve (redundant lockstep),
// warps 1-2 = prefetch next resolve column, all = MLP-friendly apply phase.
__global__ __launch_bounds__(128) void k_scan(float* __restrict__ out) {
    __shared__ u64 buf[2][64];      // double-buffered resolve column
    __shared__ u64 s_remv[NW];
    __shared__ u64 s_kb;
    int tid = threadIdx.x;
    int cnt = g_cnt_a;
    int W = (cnt + 63) >> 6;
    float f = (g_maxbox <= 0xBF800000u) ? 1.0f : (1.0f / 416.0f);

    for (int w = tid; w < NW; w += 128) s_remv[w] = 0ull;
    if (tid < 64) buf[0][tid] = (tid < cnt) ? g_mask[(size_t)tid * NW] : 0ull;
    __syncthreads();

    for (int c = 0; c < W; c++) {
        int cb = c & 1;
        if (tid < 32) {
            // branchless serial resolve, all 32 lanes redundantly (lockstep)
            u64 sup = s_remv[c];
            u64 kb = 0;
            #pragma unroll
            for (int b = 0; b < 64; b++) {
                u64 keep = ((~sup) >> b) & 1ull;
                kb |= keep << b;
                sup |= buf[cb][b] & (0ull - keep);
            }
            int lim = cnt - c * 64;
            if (lim < 64) kb &= (1ull << lim) - 1ull;
            if (tid == 0) s_kb = kb;
        } else if (tid < 96 && c + 1 < W) {
            // prefetch next chunk's resolve column (overlaps with resolve above)
            int r = (c + 1) * 64 + (tid - 32);
            buf[1 - cb][tid - 32] = (r < cnt) ? g_mask[(size_t)r * NW + (c + 1)] : 0ull;
        }
        __syncthreads();
        u64 kb = s_kb;

        // emit kept rows of this chunk at their overall sorted positions
        if (tid < 64) {
            int k = c * 64 + tid;
            if (k < cnt && ((kb >> tid) & 1ull)) {
                float* o = out + g_apos[k] * 6;
                *(float2*)(o)     = make_float2(g_sx1[k] * f, g_sy1[k] * f);
                *(float2*)(o + 2) = make_float2(g_sx2[k] * f, g_sy2[k] * f);
                *(float2*)(o + 4) = make_float2(g_ssc[k], 0.0f);
            }
        }

        // apply: (w, row-group) per thread, UNCONDITIONAL loads selected by kb -> full MLP
        int g = tid >> 4;               // 0..7, 8 rows each
        size_t base = (size_t)c * 64;
        for (int w = (tid & 15); w < W; w += 16) {
            if (w > c) {
                u64 acc = 0;
                #pragma unroll
                for (int b2 = 0; b2 < 8; b2++) {
                    int b = g * 8 + b2;
                    acc |= g_mask[(base + b) * NW + w] & (0ull - ((kb >> b) & 1ull));
                }
                if (acc) atomicOr(&s_remv[w], acc);
            }
        }
        __syncthreads();
    }

    // reset counters for the next graph replay
    if (tid == 0) { g_cnt = 0; g_cnt_a = 0; g_maxbox = 0u; }
}

extern "C" void kernel_launch(void* const* d_in, const int* in_sizes, int n_in,
                              void* d_out, int out_size) {
    const float* preds = (const float*)d_in[0];
    float* out = (float*)d_out;

    k_prep<<<N / 256, 256>>>(preds, out);
    k_rank<<<N / 256, 1024>>>(out);
    k_mask<<<128, 256>>>();
    k_scan<<<1, 128>>>(out);
}

// round 6
// speedup vs baseline: 4.5973x; 2.1512x over previous
#include <cuda_runtime.h>
#include <cstdint>

#define N 8192
#define NW 128          // max 64-bit words per active mask row (N/64)
typedef unsigned long long u64;
typedef unsigned int u32;

// ---------------- device globals (zero-initialized at module load) ----------------
__device__ u32 g_maxbox;
__device__ int g_cnt;      // valid boxes (score > 0.25)
__device__ int g_cnt_a;    // active valid boxes (positive area)
__device__ float g_x1[N], g_y1[N], g_x2[N], g_y2[N], g_sc[N];
__device__ u64 g_keys[N];  // (~mono(score))<<32 | idx<<1 | act   -- full-u64 comparable
__device__ float g_sx1[N], g_sy1[N], g_sx2[N], g_sy2[N], g_ssc[N], g_sar[N]; // sorted actives
__device__ int g_apos[N];  // sorted-active rank -> overall sorted position (output row)
__device__ u64 g_mask[N * NW];   // suppression bitmask among actives

__device__ __forceinline__ u32 fmono(float f) {
    u32 u = __float_as_uint(f);
    return (u & 0x80000000u) ? ~u : (u | 0x80000000u);
}

// decode boxes, coord max, warp-aggregated compaction of valid keys, zero output
__global__ void k_prep(const float* __restrict__ p, float* __restrict__ out) {
    int i = blockIdx.x * blockDim.x + threadIdx.x;   // grid covers exactly N
    float cx = p[i], cy = p[N + i], pw = p[2*N + i], ph = p[3*N + i], s = p[4*N + i];
    float x1 = cx - pw*0.5f, y1 = cy - ph*0.5f, x2 = cx + pw*0.5f, y2 = cy + ph*0.5f;
    g_x1[i]=x1; g_y1[i]=y1; g_x2[i]=x2; g_y2[i]=y2; g_sc[i]=s;

    int lane = threadIdx.x & 31;
    u32 m = fmono(fmaxf(fmaxf(x1,x2), fmaxf(y1,y2)));
    #pragma unroll
    for (int o = 16; o; o >>= 1) m = max(m, __shfl_xor_sync(0xffffffffu, m, o));
    if (lane == 0) atomicMax(&g_maxbox, m);

    bool valid = s > 0.25f;
    bool act = valid && (x2 > x1) && (y2 > y1);
    u32 vb = __ballot_sync(0xffffffffu, valid);
    u32 ab = __ballot_sync(0xffffffffu, act);
    if (vb) {
        int leader = __ffs(vb) - 1;
        int base = 0;
        if (lane == leader) {
            base = atomicAdd(&g_cnt, __popc(vb));
            if (ab) atomicAdd(&g_cnt_a, __popc(ab));
        }
        base = __shfl_sync(0xffffffffu, base, leader);
        if (valid) {
            int slot = base + __popc(vb & ((1u << lane) - 1u));
            g_keys[slot] = ((u64)(~fmono(s)) << 32) | ((u32)i << 1) | (act ? 1u : 0u);
        }
    }
    for (int k = i; k < N*6; k += N) out[k] = 0.0f;   // zero full output
}

// O(n^2) rank sort: 32 i per block, j-loop split 8 ways -> ~103 active blocks.
// Passive boxes (zero area) never interact -> emitted directly here.
__global__ __launch_bounds__(256) void k_rank(float* __restrict__ out) {
    __shared__ u64 sk[2048];
    int cnt = g_cnt;
    if (blockIdx.x * 32 >= cnt) return;
    int tid = threadIdx.x;
    int i = blockIdx.x * 32 + (tid >> 3);
    int part = tid & 7;

    u64 ki = (i < cnt) ? g_keys[i] : ~0ull;
    int rank_all = 0, rank_act = 0;

    for (int base = 0; base < cnt; base += 2048) {
        int lim = min(2048, cnt - base);
        __syncthreads();
        for (int t = tid; t < lim; t += 256) sk[t] = g_keys[base + t];
        __syncthreads();
        for (int j = part; j < lim; j += 8) {
            u64 kj = sk[j];
            int lt = kj < ki;                      // full-u64 compare, no masking
            rank_all += lt;
            rank_act += lt & (int)(kj & 1ull);
        }
    }
    #pragma unroll
    for (int o = 1; o < 8; o <<= 1) {
        rank_all += __shfl_xor_sync(0xffffffffu, rank_all, o);
        rank_act += __shfl_xor_sync(0xffffffffu, rank_act, o);
    }

    if (part == 0 && i < cnt) {
        int o = (int)((ki >> 1) & 0x1FFFull);
        bool act = (ki & 1ull) != 0ull;
        float x1 = g_x1[o], y1 = g_y1[o], x2 = g_x2[o], y2 = g_y2[o], s = g_sc[o];
        if (act) {
            int r = rank_act;
            g_sx1[r]=x1; g_sy1[r]=y1; g_sx2[r]=x2; g_sy2[r]=y2;
            g_ssc[r]=s;  g_sar[r]=(x2-x1)*(y2-y1);
            g_apos[r]=rank_all;
        } else {
            float f = (g_maxbox <= 0xBF800000u) ? 1.0f : (1.0f / 416.0f);
            float* o6 = out + rank_all * 6;
            o6[0]=x1*f; o6[1]=y1*f; o6[2]=x2*f; o6[3]=y2*f; o6[4]=s; o6[5]=0.0f;
        }
    }
}

// pairwise IoU bitmask among actives: grid-stride over actual upper-triangle tiles
__global__ __launch_bounds__(256) void k_mask() {
    int cnt = g_cnt_a;
    if (cnt == 0) return;
    int W = (cnt + 63) >> 6;
    int itiles = (cnt + 15) >> 4;
    int wtiles = (W + 15) >> 4;
    int ntiles = itiles * wtiles;

    __shared__ float jx1[1040], jy1[1040], jx2[1040], jy2[1040], jar[1040];
    int tid = threadIdx.x;

    for (int t = blockIdx.x; t < ntiles; t += gridDim.x) {
        int i0 = (t / wtiles) * 16;
        int w0 = (t % wtiles) * 16;
        if ((w0 + 16) * 64 <= i0) continue;   // fully below diagonal (uniform per block)

        __syncthreads();                       // smem reuse guard
        for (int tt = tid; tt < 1024; tt += 256) {
            int j = w0 * 64 + tt;
            int jm = (tt >> 6) * 65 + (tt & 63);   // +1 pad per 64 -> conflict-free
            bool ok = j < cnt;
            jx1[jm] = ok ? g_sx1[j] :  3.4e38f;
            jy1[jm] = ok ? g_sy1[j] :  3.4e38f;
            jx2[jm] = ok ? g_sx2[j] : -3.4e38f;
            jy2[jm] = ok ? g_sy2[j] : -3.4e38f;
            jar[jm] = ok ? g_sar[j] : 0.0f;
        }
        __syncthreads();

        int r  = tid >> 4;          // row within tile
        int wl = tid & 15;          // word within tile
        int i = i0 + r;
        int w = w0 + wl;
        if (i < cnt && w < W) {
            float ix1 = g_sx1[i], iy1 = g_sy1[i], ix2 = g_sx2[i], iy2 = g_sy2[i], iar = g_sar[i];
            int base = wl * 65;
            u64 bits = 0;
            #pragma unroll 8
            for (int jj = 0; jj < 64; jj++) {
                float bx1 = jx1[base + jj], by1 = jy1[base + jj];
                float bx2 = jx2[base + jj], by2 = jy2[base + jj], ba = jar[base + jj];
                float xx1 = fmaxf(ix1, bx1), yy1 = fmaxf(iy1, by1);
                float xx2 = fminf(ix2, bx2), yy2 = fminf(iy2, by2);
                float dx = fmaxf(xx2 - xx1, 0.0f), dy = fmaxf(yy2 - yy1, 0.0f);
                float inter = dx * dy;
                float uni = iar + ba - inter;
                bool pred = (inter > 0.45f * uni) && (uni > 0.0f);
                bits |= ((u64)pred) << jj;
            }
            g_mask[(size_t)i * NW + w] = bits;
        }
    }
}

// software-pipelined greedy scan: warp0 resolves chunk c while warps1-3
// apply/emit chunk c-1 and prefetch chunk c+1. One barrier per chunk.
// warp0 carries "delta" = chunk c's kept-row contribution to word c+1, so the
// resolve never waits on the apply phase.
__global__ __launch_bounds__(128) void k_scan(float* __restrict__ out) {
    __shared__ u64 colbuf[2][64];    // resolve column of chunk c (word c)
    __shared__ u64 nextbuf[2][64];   // rows of chunk c at word c+1 (for delta)
    __shared__ u64 s_remv[NW];
    __shared__ u64 s_kb[2];
    int tid = threadIdx.x;
    int cnt = g_cnt_a;
    int W = (cnt + 63) >> 6;
    float f = (g_maxbox <= 0xBF800000u) ? 1.0f : (1.0f / 416.0f);

    for (int w = tid; w < NW; w += 128) s_remv[w] = 0ull;
    if (tid < 64 && W > 0) {
        int r = tid;
        colbuf[0][tid]  = (r < cnt) ? g_mask[(size_t)r * NW + 0] : 0ull;
        nextbuf[0][tid] = (W > 1 && r < cnt) ? g_mask[(size_t)r * NW + 1] : 0ull;
    }
    __syncthreads();

    u64 delta = 0;                   // live in warp0 registers across iterations
    for (int c = 0; c < W; c++) {
        int cb = c & 1;
        if (tid < 32) {
            // ---- serial branchless resolve of chunk c (all lanes redundant) ----
            u64 sup = s_remv[c] | delta;
            const u64* col = colbuf[cb];
            u64 kb = 0;
            #pragma unroll
            for (int g8 = 0; g8 < 8; g8++) {
                u64 m[8];
                #pragma unroll
                for (int b = 0; b < 8; b++) m[b] = col[g8 * 8 + b];
                #pragma unroll
                for (int b = 0; b < 8; b++) {
                    int bb = g8 * 8 + b;
                    u64 keep = ((~sup) >> bb) & 1ull;
                    kb |= keep << bb;
                    sup |= m[b] & (0ull - keep);
                }
            }
            int lim = cnt - c * 64;
            if (lim < 64) kb &= (1ull << lim) - 1ull;
            if (tid == 0) s_kb[cb] = kb;
            // ---- delta for word c+1 (independent loads, no chain) ----
            delta = 0;
            if (c + 1 < W) {
                const u64* nxt = nextbuf[cb];
                #pragma unroll
                for (int bb = 0; bb < 64; bb++)
                    delta |= nxt[bb] & (0ull - ((kb >> bb) & 1ull));
            }
        } else {
            int t = tid - 32;        // 0..95
            if (c >= 1) {
                u64 kbp = s_kb[1 - cb];
                // emit chunk c-1's kept rows
                if (t < 64) {
                    int k = (c - 1) * 64 + t;
                    if (k < cnt && ((kbp >> t) & 1ull)) {
                        float* o = out + g_apos[k] * 6;
                        *(float2*)(o)     = make_float2(g_sx1[k] * f, g_sy1[k] * f);
                        *(float2*)(o + 2) = make_float2(g_sx2[k] * f, g_sy2[k] * f);
                        *(float2*)(o + 4) = make_float2(g_ssc[k], 0.0f);
                    }
                }
                // apply chunk c-1 to words >= c+1 (word c was handled via delta)
                int g = t & 7;
                size_t rb = (size_t)(c - 1) * 64;
                for (int w = c + 1 + (t >> 3); w < W; w += 12) {
                    u64 acc = 0;
                    #pragma unroll
                    for (int b2 = 0; b2 < 8; b2++) {
                        int b = g * 8 + b2;
                        acc |= g_mask[(rb + b) * NW + w] & (0ull - ((kbp >> b) & 1ull));
                    }
                    if (acc) atomicOr(&s_remv[w], acc);
                }
            }
            // prefetch chunk c+1 columns
            if (c + 1 < W) {
                if (t < 64) {
                    int r = (c + 1) * 64 + t;
                    colbuf[1 - cb][t] = (r < cnt) ? g_mask[(size_t)r * NW + (c + 1)] : 0ull;
                } else {
                    #pragma unroll
                    for (int h = 0; h < 2; h++) {
                        int rr = (t - 64) * 2 + h;
                        int r = (c + 1) * 64 + rr;
                        nextbuf[1 - cb][rr] =
                            (c + 2 < W && r < cnt) ? g_mask[(size_t)r * NW + (c + 2)] : 0ull;
                    }
                }
            }
        }
        __syncthreads();
    }

    // epilogue: emit last chunk's kept rows
    if (W > 0 && tid < 64) {
        u64 kbl = s_kb[(W - 1) & 1];
        int k = (W - 1) * 64 + tid;
        if (k < cnt && ((kbl >> tid) & 1ull)) {
            float* o = out + g_apos[k] * 6;
            *(float2*)(o)     = make_float2(g_sx1[k] * f, g_sy1[k] * f);
            *(float2*)(o + 2) = make_float2(g_sx2[k] * f, g_sy2[k] * f);
            *(float2*)(o + 4) = make_float2(g_ssc[k], 0.0f);
        }
    }

    // reset counters for the next graph replay
    if (tid == 0) { g_cnt = 0; g_cnt_a = 0; g_maxbox = 0u; }
}

extern "C" void kernel_launch(void* const* d_in, const int* in_sizes, int n_in,
                              void* d_out, int out_size) {
    const float* preds = (const float*)d_in[0];
    float* out = (float*)d_out;

    k_prep<<<N / 256, 256>>>(preds, out);
    k_rank<<<256, 256>>>(out);          // 32 i per block; excess blocks exit
    k_mask<<<128, 256>>>();
    k_scan<<<1, 128>>>(out);
}